// round 15
// baseline (speedup 1.0000x reference)
#include <cuda_runtime.h>
#include <cuda_fp16.h>
#include <cstdint>

// out[b,h,o] = sum_{i,d} x[b,h,i,d] * ws[o,i] * weight[o,d]
// => C (8192x1024) = A (8192x4096) . W2^T,  W2[n,k] = ws[n,k>>2]*weight[n,k&3]
// Single-term fp16 HMMA GEMM. This round: CTA tile 128x256 (256 threads,
// 2x4 warp grid of 64x64 warp tiles, 1 CTA/SM) -- per-iteration fixed overhead
// (barrier + ldsm lead-in) amortized over 2x tensor work; barrier events and
// B-tile L2 reads halved. Inner-loop ordering = the proven R9 schedule.

#define M_DIM 8192
#define N_DIM 1024
#define K_DIM 4096
#define BM 128
#define BN 256
#define BK 32
#define KT (K_DIM / BK)        // 128
#define ROWB 80                // 32 f16 (64B) + 16B pad -> conflict-free ldmatrix
#define TILE_A (128 * ROWB)    // 10240 B
#define TILE_B (256 * ROWB)    // 20480 B
#define STAGE (TILE_A + TILE_B) // 30720 B
#define NSTAGE 4
#define SMEM_BYTES (NSTAGE * STAGE)   // 122880 B -> 1 CTA/SM (regs cap it anyway)

// Precomputed fp16 operands (plain row-major).
__device__ __half g_a[(size_t)M_DIM * K_DIM];
__device__ __half g_b[(size_t)N_DIM * K_DIM];

// ---------------------------------------------------------------- helpers
__device__ __forceinline__ void ldsm_x4(uint32_t* r, uint32_t addr) {
    asm volatile("ldmatrix.sync.aligned.m8n8.x4.shared.b16 {%0,%1,%2,%3}, [%4];"
                 : "=r"(r[0]), "=r"(r[1]), "=r"(r[2]), "=r"(r[3]) : "r"(addr));
}
__device__ __forceinline__ void mma16816(float* c, const uint32_t* a, const uint32_t* b) {
    asm volatile(
        "mma.sync.aligned.m16n8k16.row.col.f32.f16.f16.f32 "
        "{%0,%1,%2,%3}, {%4,%5,%6,%7}, {%8,%9}, {%0,%1,%2,%3};"
        : "+f"(c[0]), "+f"(c[1]), "+f"(c[2]), "+f"(c[3])
        : "r"(a[0]), "r"(a[1]), "r"(a[2]), "r"(a[3]), "r"(b[0]), "r"(b[1]));
}
__device__ __forceinline__ void cp16(uint32_t dst, const void* src) {
    asm volatile("cp.async.cg.shared.global [%0], [%1], 16;"
                 :: "r"(dst), "l"(src) : "memory");
}
__device__ __forceinline__ uint32_t pack_h2(float a, float b) {
    uint32_t r;
    asm volatile("cvt.rn.f16x2.f32 %0, %1, %2;" : "=r"(r) : "f"(b), "f"(a));
    return r;
}

// ------------------------- merged conversion: x -> g_a, (ws,weight) -> g_b
__global__ __launch_bounds__(256) void convert_all(const float* __restrict__ x,
                                                   const float* __restrict__ weight,
                                                   const float* __restrict__ ws) {
    if (blockIdx.x < 16384) {
        size_t idx = (size_t)blockIdx.x * 256 + threadIdx.x;   // 4,194,304 threads
        size_t base = idx * 8;
        float4 t0 = *(const float4*)(x + base);
        float4 t1 = *(const float4*)(x + base + 4);
        uint4 o;
        o.x = pack_h2(t0.x, t0.y);
        o.y = pack_h2(t0.z, t0.w);
        o.z = pack_h2(t1.x, t1.y);
        o.w = pack_h2(t1.z, t1.w);
        *(uint4*)(g_a + base) = o;
    } else {
        size_t idx = (size_t)(blockIdx.x - 16384) * 256 + threadIdx.x;  // 524,288
        int n  = (int)(idx >> 9);
        int kk = ((int)idx & 511) * 8;     // 8 consecutive k = 2 i-values x 4 d
        int i0 = kk >> 2;
        float2 sv = *(const float2*)(ws + (size_t)n * 1024 + i0);
        float4 wv = *(const float4*)(weight + n * 4);
        uint4 o;
        o.x = pack_h2(sv.x * wv.x, sv.x * wv.y);
        o.y = pack_h2(sv.x * wv.z, sv.x * wv.w);
        o.z = pack_h2(sv.y * wv.x, sv.y * wv.y);
        o.w = pack_h2(sv.y * wv.z, sv.y * wv.w);
        *(uint4*)(g_b + (size_t)n * K_DIM + kk) = o;
    }
}

// ----------------------------------------------------------- HMMA GEMM
__global__ __launch_bounds__(256, 1)
void gemm_mma(float* __restrict__ out) {
    extern __shared__ uint8_t smem[];
    uint32_t sbase = (uint32_t)__cvta_generic_to_shared(smem);

    const int tid = threadIdx.x, lane = tid & 31, wid = tid >> 5;
    const int wm = wid >> 2;          // 0..1  (64 rows)
    const int wn = wid & 3;           // 0..3  (64 cols)
    const int nt = blockIdx.x, mt = blockIdx.y;

    float c[4][8][4];
#pragma unroll
    for (int i = 0; i < 4; i++)
#pragma unroll
        for (int j = 0; j < 8; j++)
#pragma unroll
            for (int q = 0; q < 4; q++) c[i][j][q] = 0.0f;

    const __half* asrc = g_a + (size_t)mt * BM * K_DIM;
    const __half* bsrc = g_b + (size_t)nt * BN * K_DIM;

    auto issue = [&](int kt) {
        int k0 = kt * BK;
        uint32_t sst = sbase + (kt % NSTAGE) * STAGE;
        // A tile: 128 rows x 4 chunks = 512 -> 2 per thread
#pragma unroll
        for (int it = 0; it < 2; it++) {
            int idx = it * 256 + tid;          // 0..511
            int row = idx >> 2, ch = idx & 3;
            cp16(sst + row * ROWB + ch * 16,
                 asrc + (size_t)row * K_DIM + k0 + ch * 8);
        }
        // B tile: 256 rows x 4 chunks = 1024 -> 4 per thread
#pragma unroll
        for (int it = 0; it < 4; it++) {
            int idx = it * 256 + tid;          // 0..1023
            int row = idx >> 2, ch = idx & 3;
            cp16(sst + TILE_A + row * ROWB + ch * 16,
                 bsrc + (size_t)row * K_DIM + k0 + ch * 8);
        }
    };

    // fragment smem addressing (constant per thread)
    const int rA = wm * 64 + (lane & 15);                          // + mf*16
    const uint32_t kAofs = (((uint32_t)lane >> 4) & 1) * 8;        // + ks*16
    const int rB = wn * 64 + (lane & 7) + (((lane >> 4) & 1) * 8); // + nh*16
    const uint32_t kBofs = (((uint32_t)lane >> 3) & 1) * 8;

    // prologue: fill 3 of 4 stages
    issue(0); asm volatile("cp.async.commit_group;" ::: "memory");
    issue(1); asm volatile("cp.async.commit_group;" ::: "memory");
    issue(2); asm volatile("cp.async.commit_group;" ::: "memory");

    for (int kt = 0; kt < KT; kt++) {
        asm volatile("cp.async.wait_group 2;" ::: "memory");
        __syncthreads();

        uint32_t sA = sbase + (kt % NSTAGE) * STAGE;
        uint32_t sB = sA + TILE_A;

#pragma unroll
        for (int ks = 0; ks < 2; ks++) {
            uint32_t ka = (ks * 16 + kAofs) * 2;
            uint32_t kb = (ks * 16 + kBofs) * 2;
            uint32_t ah[4][4], bh[4][4];
#pragma unroll
            for (int nh = 0; nh < 4; nh++)
                ldsm_x4(bh[nh], sB + (uint32_t)(rB + nh * 16) * ROWB + kb);
#pragma unroll
            for (int mf = 0; mf < 4; mf++)
                ldsm_x4(ah[mf], sA + (uint32_t)(rA + mf * 16) * ROWB + ka);

#pragma unroll
            for (int mf = 0; mf < 4; mf++)
#pragma unroll
                for (int nf = 0; nf < 8; nf++)
                    mma16816(c[mf][nf], ah[mf], &bh[nf >> 1][(nf & 1) * 2]);
        }

        // refill at loop bottom -- the proven ordering
        if (kt + 3 < KT) issue(kt + 3);
        asm volatile("cp.async.commit_group;" ::: "memory");
    }

    // ---- epilogue ----
    const int gid = lane >> 2, tig = lane & 3;
#pragma unroll
    for (int mf = 0; mf < 4; mf++) {
#pragma unroll
        for (int nf = 0; nf < 8; nf++) {
            int r0 = mt * BM + wm * 64 + mf * 16 + gid;
            int col = nt * BN + wn * 64 + nf * 8 + tig * 2;
            float* p = out + (size_t)r0 * N_DIM + col;
            *(float2*)p = make_float2(c[mf][nf][0], c[mf][nf][1]);
            *(float2*)(p + 8 * N_DIM) = make_float2(c[mf][nf][2], c[mf][nf][3]);
        }
    }
}

// ---------------------------------------------------------------- launcher
extern "C" void kernel_launch(void* const* d_in, const int* in_sizes, int n_in,
                              void* d_out, int out_size) {
    const float* x      = (const float*)d_in[0];   // (4,2048,1024,4)
    const float* weight = (const float*)d_in[1];   // (1024,4)
    const float* ws     = (const float*)d_in[2];   // (1024,1024)
    float* out          = (float*)d_out;           // (4,2048,1024)

    convert_all<<<16384 + 2048, 256>>>(x, weight, ws);

    cudaFuncSetAttribute(gemm_mma, cudaFuncAttributeMaxDynamicSharedMemorySize, SMEM_BYTES);
    dim3 grid(N_DIM / BN, M_DIM / BM);   // (4, 64), nt fastest for L2 reuse of A
    gemm_mma<<<grid, 256, SMEM_BYTES>>>(out);
}

// round 16
// speedup vs baseline: 1.2368x; 1.2368x over previous
#include <cuda_runtime.h>
#include <cuda_fp16.h>
#include <cstdint>

// out[b,h,o] = sum_{i,d} x[b,h,i,d] * ws[o,i] * weight[o,d]
// => C (8192x1024) = A (8192x4096) . W2^T,  W2[n,k] = ws[n,k>>2]*weight[n,k&3]
// Single-term fp16 HMMA GEMM, R14 champion shape (2x2 warp grid, 64x64 warp
// tiles, BK=32, 2 CTAs/SM). This round: NSTAGE 4->5 with issue(kt+3) so the
// rewritten stage is 2 iterations stale -- __syncthreads only every OTHER
// iteration. Barrier events halve and warps can drift to cover ldsm bursts.

#define M_DIM 8192
#define N_DIM 1024
#define K_DIM 4096
#define BM 128
#define BN 128
#define BK 32
#define KT (K_DIM / BK)        // 128
#define ROWB 80                // 32 f16 (64B) + 16B pad -> conflict-free ldmatrix
#define TILE_B (128 * ROWB)    // 10240 B per tile
#define STAGE (2 * TILE_B)     // A tile + B tile = 20480 B
#define NSTAGE 5
#define SMEM_BYTES (NSTAGE * STAGE)   // 102400 B -> 2 CTAs/SM

// Precomputed fp16 operands (plain row-major).
__device__ __half g_a[(size_t)M_DIM * K_DIM];
__device__ __half g_b[(size_t)N_DIM * K_DIM];

// ---------------------------------------------------------------- helpers
__device__ __forceinline__ void ldsm_x4(uint32_t* r, uint32_t addr) {
    asm volatile("ldmatrix.sync.aligned.m8n8.x4.shared.b16 {%0,%1,%2,%3}, [%4];"
                 : "=r"(r[0]), "=r"(r[1]), "=r"(r[2]), "=r"(r[3]) : "r"(addr));
}
__device__ __forceinline__ void mma16816(float* c, const uint32_t* a, const uint32_t* b) {
    asm volatile(
        "mma.sync.aligned.m16n8k16.row.col.f32.f16.f16.f32 "
        "{%0,%1,%2,%3}, {%4,%5,%6,%7}, {%8,%9}, {%0,%1,%2,%3};"
        : "+f"(c[0]), "+f"(c[1]), "+f"(c[2]), "+f"(c[3])
        : "r"(a[0]), "r"(a[1]), "r"(a[2]), "r"(a[3]), "r"(b[0]), "r"(b[1]));
}
__device__ __forceinline__ void cp16(uint32_t dst, const void* src) {
    asm volatile("cp.async.cg.shared.global [%0], [%1], 16;"
                 :: "r"(dst), "l"(src) : "memory");
}
__device__ __forceinline__ uint32_t pack_h2(float a, float b) {
    uint32_t r;
    asm volatile("cvt.rn.f16x2.f32 %0, %1, %2;" : "=r"(r) : "f"(b), "f"(a));
    return r;
}

// ------------------------- merged conversion: x -> g_a, (ws,weight) -> g_b
__global__ __launch_bounds__(256) void convert_all(const float* __restrict__ x,
                                                   const float* __restrict__ weight,
                                                   const float* __restrict__ ws) {
    if (blockIdx.x < 16384) {
        size_t idx = (size_t)blockIdx.x * 256 + threadIdx.x;   // 4,194,304 threads
        size_t base = idx * 8;
        float4 t0 = *(const float4*)(x + base);
        float4 t1 = *(const float4*)(x + base + 4);
        uint4 o;
        o.x = pack_h2(t0.x, t0.y);
        o.y = pack_h2(t0.z, t0.w);
        o.z = pack_h2(t1.x, t1.y);
        o.w = pack_h2(t1.z, t1.w);
        *(uint4*)(g_a + base) = o;
    } else {
        size_t idx = (size_t)(blockIdx.x - 16384) * 256 + threadIdx.x;  // 524,288
        int n  = (int)(idx >> 9);
        int kk = ((int)idx & 511) * 8;     // 8 consecutive k = 2 i-values x 4 d
        int i0 = kk >> 2;
        float2 sv = *(const float2*)(ws + (size_t)n * 1024 + i0);
        float4 wv = *(const float4*)(weight + n * 4);
        uint4 o;
        o.x = pack_h2(sv.x * wv.x, sv.x * wv.y);
        o.y = pack_h2(sv.x * wv.z, sv.x * wv.w);
        o.z = pack_h2(sv.y * wv.x, sv.y * wv.y);
        o.w = pack_h2(sv.y * wv.z, sv.y * wv.w);
        *(uint4*)(g_b + (size_t)n * K_DIM + kk) = o;
    }
}

// ----------------------------------------------------------- HMMA GEMM
__global__ __launch_bounds__(128, 2)
void gemm_mma(float* __restrict__ out) {
    extern __shared__ uint8_t smem[];
    uint32_t sbase = (uint32_t)__cvta_generic_to_shared(smem);

    const int tid = threadIdx.x, lane = tid & 31, wid = tid >> 5;
    const int wm = wid >> 1;          // 0..1  (64 rows)
    const int wn = wid & 1;           // 0..1  (64 cols)
    const int nt = blockIdx.x, mt = blockIdx.y;

    float c[4][8][4];
#pragma unroll
    for (int i = 0; i < 4; i++)
#pragma unroll
        for (int j = 0; j < 8; j++)
#pragma unroll
            for (int q = 0; q < 4; q++) c[i][j][q] = 0.0f;

    const __half* asrc = g_a + (size_t)mt * BM * K_DIM;
    const __half* bsrc = g_b + (size_t)nt * BN * K_DIM;

    auto issue = [&](int kt) {
        int k0 = kt * BK;
        uint32_t sst = sbase + (kt % NSTAGE) * STAGE;
#pragma unroll
        for (int it = 0; it < 4; it++) {
            int idx = it * 128 + tid;          // 0..511
            int row = idx >> 2, ch = idx & 3;  // 128 rows x 4 chunks
            cp16(sst + row * ROWB + ch * 16,
                 asrc + (size_t)row * K_DIM + k0 + ch * 8);
        }
#pragma unroll
        for (int it = 0; it < 4; it++) {
            int idx = it * 128 + tid;
            int row = idx >> 2, ch = idx & 3;
            cp16(sst + TILE_B + row * ROWB + ch * 16,
                 bsrc + (size_t)row * K_DIM + k0 + ch * 8);
        }
    };

    // fragment smem addressing (constant per thread)
    const int rA = wm * 64 + (lane & 15);                          // + mf*16
    const uint32_t kAofs = (((uint32_t)lane >> 4) & 1) * 8;        // + ks*16
    const int rB = wn * 64 + (lane & 7) + (((lane >> 4) & 1) * 8); // + nh*16
    const uint32_t kBofs = (((uint32_t)lane >> 3) & 1) * 8;

    // prologue: fill 3 of 5 stages
    issue(0); asm volatile("cp.async.commit_group;" ::: "memory");
    issue(1); asm volatile("cp.async.commit_group;" ::: "memory");
    issue(2); asm volatile("cp.async.commit_group;" ::: "memory");

    for (int kt = 0; kt < KT; kt++) {
        asm volatile("cp.async.wait_group 2;" ::: "memory");
        // Barrier every OTHER iteration: the stage rewritten at the bottom of
        // iter kt is (kt+3)%5 == (kt-2)%5, last read at iter kt-2. The barrier
        // at the top of even kt covers all reads through iter kt-1, which
        // protects the rewrites issued at the bottoms of both kt and kt+1.
        if ((kt & 1) == 0) __syncthreads();

        uint32_t sA = sbase + (kt % NSTAGE) * STAGE;
        uint32_t sB = sA + TILE_B;

#pragma unroll
        for (int ks = 0; ks < 2; ks++) {
            uint32_t ka = (ks * 16 + kAofs) * 2;
            uint32_t kb = (ks * 16 + kBofs) * 2;
            uint32_t ah[4][4], bh[4][4];
#pragma unroll
            for (int nh = 0; nh < 4; nh++)
                ldsm_x4(bh[nh], sB + (uint32_t)(rB + nh * 16) * ROWB + kb);
#pragma unroll
            for (int mf = 0; mf < 4; mf++)
                ldsm_x4(ah[mf], sA + (uint32_t)(rA + mf * 16) * ROWB + ka);

#pragma unroll
            for (int mf = 0; mf < 4; mf++)
#pragma unroll
                for (int nf = 0; nf < 8; nf++)
                    mma16816(c[mf][nf], ah[mf], &bh[nf >> 1][(nf & 1) * 2]);
        }

        // refill at loop bottom -- the proven ordering
        if (kt + 3 < KT) issue(kt + 3);
        asm volatile("cp.async.commit_group;" ::: "memory");
    }

    // ---- epilogue ----
    const int gid = lane >> 2, tig = lane & 3;
#pragma unroll
    for (int mf = 0; mf < 4; mf++) {
#pragma unroll
        for (int nf = 0; nf < 8; nf++) {
            int r0 = mt * BM + wm * 64 + mf * 16 + gid;
            int col = nt * BN + wn * 64 + nf * 8 + tig * 2;
            float* p = out + (size_t)r0 * N_DIM + col;
            *(float2*)p = make_float2(c[mf][nf][0], c[mf][nf][1]);
            *(float2*)(p + 8 * N_DIM) = make_float2(c[mf][nf][2], c[mf][nf][3]);
        }
    }
}

// ---------------------------------------------------------------- launcher
extern "C" void kernel_launch(void* const* d_in, const int* in_sizes, int n_in,
                              void* d_out, int out_size) {
    const float* x      = (const float*)d_in[0];   // (4,2048,1024,4)
    const float* weight = (const float*)d_in[1];   // (1024,4)
    const float* ws     = (const float*)d_in[2];   // (1024,1024)
    float* out          = (float*)d_out;           // (4,2048,1024)

    convert_all<<<16384 + 2048, 256>>>(x, weight, ws);

    cudaFuncSetAttribute(gemm_mma, cudaFuncAttributeMaxDynamicSharedMemorySize, SMEM_BYTES);
    dim3 grid(N_DIM / BN, M_DIM / BM);   // (8, 64), nt fastest for L2 reuse of A
    gemm_mma<<<grid, 128, SMEM_BYTES>>>(out);
}